// round 7
// baseline (speedup 1.0000x reference)
#include <cuda_runtime.h>
#include <cuda_fp16.h>
#include <cstdint>

// ============================================================================
// BinaryLinear: y = x @ sign(W)^T + sign(b)
//   x [8192,4096] f32, W [4096,4096] f32, b [4096] f32 -> y [8192,4096] f32
// fp32 -> fp16 convert pre-pass, then mma.sync.m16n8k16 (HMMA) GEMM:
// 256x128 CTA tile, 256 threads (8 warps, 4x2), warp tile 64x64,
// BK=128, 2-stage cp.async pipeline (192KB smem), fp32 accum, fused sign(bias).
// ============================================================================

#define TOKENS 8192
#define KDIM   4096
#define NDIM   4096

#define BM 256
#define BN 128
#define BK 128
#define NKIT   (KDIM / BK)          // 32
#define TILES_N (NDIM / BN)         // 32
#define TILES_M (TOKENS / BM)       // 32

#define ROWB 256                               // smem row bytes (BK * 2)
#define A_STAGE_BYTES (BM * ROWB)              // 65536
#define B_STAGE_BYTES (BN * ROWB)              // 32768
#define STAGE_BYTES   (A_STAGE_BYTES + B_STAGE_BYTES)   // 98304
#define SMEM_TOTAL    (2 * STAGE_BYTES)        // 196608

__device__ __half g_xh[(size_t)TOKENS * KDIM];   // 64 MB scratch
__device__ __half g_wh[(size_t)NDIM * KDIM];     // 32 MB scratch

// ---------------------------------------------------------------------------
// helpers
// ---------------------------------------------------------------------------
__device__ __forceinline__ uint32_t smem_u32(const void* p) {
    uint32_t a;
    asm("{ .reg .u64 t; cvta.to.shared.u64 t, %1; cvt.u32.u64 %0, t; }"
        : "=r"(a) : "l"(p));
    return a;
}

__device__ __forceinline__ void cp16(uint32_t saddr, const void* gaddr) {
    asm volatile("cp.async.cg.shared.global [%0], [%1], 16;"
                 :: "r"(saddr), "l"(gaddr));
}

__device__ __forceinline__ void ldsm4(uint32_t* r, uint32_t addr) {
    asm volatile("ldmatrix.sync.aligned.m8n8.x4.shared.b16 {%0,%1,%2,%3}, [%4];"
                 : "=r"(r[0]), "=r"(r[1]), "=r"(r[2]), "=r"(r[3]) : "r"(addr));
}

__device__ __forceinline__ void mma16816(float* d, const uint32_t* a,
                                         uint32_t b0, uint32_t b1) {
    asm volatile(
        "mma.sync.aligned.m16n8k16.row.col.f32.f16.f16.f32 "
        "{%0,%1,%2,%3}, {%4,%5,%6,%7}, {%8,%9}, {%0,%1,%2,%3};"
        : "+f"(d[0]), "+f"(d[1]), "+f"(d[2]), "+f"(d[3])
        : "r"(a[0]), "r"(a[1]), "r"(a[2]), "r"(a[3]), "r"(b0), "r"(b1));
}

// Swizzle for 256B rows: 16 16B-chunks per row; chunk' = chunk ^ (row & 7).
// Producer: 256 threads; A: 256 rows x 16 chunks = 4096 cp16 -> 16/thread;
// B: 128 rows x 16 chunks = 2048 -> 8/thread.
__device__ __forceinline__ void load_stage(uint32_t sb, int buf,
                                           const __half* Ag, const __half* Bg,
                                           int kofs, int tid) {
    uint32_t bufA = sb + (uint32_t)buf * STAGE_BYTES;
    uint32_t bufB = bufA + A_STAGE_BYTES;
    const int row0 = tid >> 4;          // 0..15
    const int kc = tid & 15;
    const uint32_t sw0 = (uint32_t)row0 * ROWB
                       + ((uint32_t)(kc ^ (row0 & 7)) << 4);
    const __half* ga = Ag + (size_t)row0 * KDIM + kofs + kc * 8;
    const __half* gb = Bg + (size_t)row0 * KDIM + kofs + kc * 8;
    #pragma unroll
    for (int it = 0; it < 16; it++) {   // A rows: row0 + 16*it (16%8==0)
        uint32_t sw = sw0 + (uint32_t)it * 16 * ROWB;
        cp16(bufA + sw, ga + (size_t)it * 16 * KDIM);
    }
    #pragma unroll
    for (int it = 0; it < 8; it++) {    // B rows: row0 + 16*it
        uint32_t sw = sw0 + (uint32_t)it * 16 * ROWB;
        cp16(bufB + sw, gb + (size_t)it * 16 * KDIM);
    }
}

// ---------------------------------------------------------------------------
// Pre-pass: fp32 -> fp16 conversions
// ---------------------------------------------------------------------------
__global__ void __launch_bounds__(256) k_cvt_x(const float4* __restrict__ x) {
    int i = blockIdx.x * 256 + threadIdx.x;
    float4 v = x[i];
    __half2 h0 = __floats2half2_rn(v.x, v.y);
    __half2 h1 = __floats2half2_rn(v.z, v.w);
    uint2 o;
    o.x = *reinterpret_cast<uint32_t*>(&h0);
    o.y = *reinterpret_cast<uint32_t*>(&h1);
    reinterpret_cast<uint2*>(g_xh)[i] = o;
}

__global__ void __launch_bounds__(256) k_cvt_w(const float4* __restrict__ w) {
    int i = blockIdx.x * 256 + threadIdx.x;
    float4 v = w[i];
    __half2 h0 = __floats2half2_rn(v.x >= 0.f ? 1.f : -1.f,
                                   v.y >= 0.f ? 1.f : -1.f);
    __half2 h1 = __floats2half2_rn(v.z >= 0.f ? 1.f : -1.f,
                                   v.w >= 0.f ? 1.f : -1.f);
    uint2 o;
    o.x = *reinterpret_cast<uint32_t*>(&h0);
    o.y = *reinterpret_cast<uint32_t*>(&h1);
    reinterpret_cast<uint2*>(g_wh)[i] = o;
}

// ---------------------------------------------------------------------------
// HMMA GEMM: 8 warps (4 warpM x 2 warpN), warp tile 64x64.
// ---------------------------------------------------------------------------
__global__ void __launch_bounds__(256, 1) binlin_gemm(const float* __restrict__ bias,
                                                      float* __restrict__ out) {
    extern __shared__ char smem[];
    const uint32_t sb = smem_u32(smem);
    const int tid = threadIdx.x;
    const int wid = tid >> 5;
    const int lid = tid & 31;

    const int tileN = blockIdx.x % TILES_N;   // consecutive bids share tileM:
    const int tileM = blockIdx.x / TILES_N;   // A reuse + W resident in L2
    const int m0 = tileM * BM;
    const int n0 = tileN * BN;

    const __half* Ag = g_xh + (size_t)m0 * KDIM;
    const __half* Bg = g_wh + (size_t)n0 * KDIM;

    const int warpM = wid >> 1;               // 0..3 -> 64-row slices
    const int warpN = wid & 1;                // 0..1 -> 64-col slices

    // ldmatrix lane address components
    const int rowa = warpM * 64 + (lid & 15);
    const int ka   = lid >> 4;                // A: k8-half select
    const int rowb = warpN * 64 + (lid & 7) + ((lid >> 4) << 3);
    const int kb   = (lid >> 3) & 1;          // B: k8-half select
    const uint32_t offA0 = (uint32_t)rowa * ROWB;
    const uint32_t offB0 = (uint32_t)rowb * ROWB;
    const int ra7 = rowa & 7;
    const int rb7 = rowb & 7;

    float acc[4][8][4];
    #pragma unroll
    for (int i = 0; i < 4; i++)
        #pragma unroll
        for (int j = 0; j < 8; j++)
            #pragma unroll
            for (int r = 0; r < 4; r++) acc[i][j][r] = 0.f;

    // prologue: fill stage 0
    load_stage(sb, 0, Ag, Bg, 0, tid);
    asm volatile("cp.async.commit_group;" ::: "memory");

    int buf_rd = 0;
    int buf_ld = 1;

    for (int kt = 0; kt < NKIT; kt++) {
        asm volatile("cp.async.wait_group 0;" ::: "memory");
        __syncthreads();

        const int knext = kt + 1;
        if (knext < NKIT)
            load_stage(sb, buf_ld, Ag, Bg, knext * BK, tid);
        asm volatile("cp.async.commit_group;" ::: "memory");
        buf_ld ^= 1;

        const uint32_t bufA = sb + (uint32_t)buf_rd * STAGE_BYTES;
        const uint32_t bufB = bufA + A_STAGE_BYTES;
        buf_rd ^= 1;

        #pragma unroll
        for (int ks = 0; ks < 8; ks++) {
            uint32_t a_r[4][4], b_r[4][4];
            #pragma unroll
            for (int mi = 0; mi < 4; mi++) {
                uint32_t ad = bufA + offA0 + (uint32_t)(mi * 16 * ROWB)
                            + ((uint32_t)((ks * 2 + ka) ^ ra7) << 4);
                ldsm4(a_r[mi], ad);
            }
            #pragma unroll
            for (int nj = 0; nj < 4; nj++) {
                uint32_t bd = bufB + offB0 + (uint32_t)(nj * 16 * ROWB)
                            + ((uint32_t)((ks * 2 + kb) ^ rb7) << 4);
                ldsm4(b_r[nj], bd);
            }
            #pragma unroll
            for (int mi = 0; mi < 4; mi++)
                #pragma unroll
                for (int n8 = 0; n8 < 8; n8++)
                    mma16816(acc[mi][n8], a_r[mi],
                             b_r[n8 >> 1][(n8 & 1) * 2],
                             b_r[n8 >> 1][(n8 & 1) * 2 + 1]);
        }
    }

    // epilogue: fused sign(bias), float2 stores
    const int m0w = m0 + warpM * 64;
    const int n0w = n0 + warpN * 64;
    const int rr = lid >> 2;
    const int cq = (lid & 3) * 2;

    float sb0[8], sb1[8];
    #pragma unroll
    for (int n8 = 0; n8 < 8; n8++) {
        int c = n0w + n8 * 8 + cq;
        sb0[n8] = bias[c]     >= 0.f ? 1.f : -1.f;
        sb1[n8] = bias[c + 1] >= 0.f ? 1.f : -1.f;
    }

    #pragma unroll
    for (int mi = 0; mi < 4; mi++) {
        const int r1 = m0w + mi * 16 + rr;
        #pragma unroll
        for (int n8 = 0; n8 < 8; n8++) {
            const int c = n0w + n8 * 8 + cq;
            float2 v1, v2;
            v1.x = acc[mi][n8][0] + sb0[n8];
            v1.y = acc[mi][n8][1] + sb1[n8];
            v2.x = acc[mi][n8][2] + sb0[n8];
            v2.y = acc[mi][n8][3] + sb1[n8];
            *reinterpret_cast<float2*>(out + (size_t)r1 * NDIM + c) = v1;
            *reinterpret_cast<float2*>(out + (size_t)(r1 + 8) * NDIM + c) = v2;
        }
    }
}

// ---------------------------------------------------------------------------
// Entry point
// ---------------------------------------------------------------------------
extern "C" void kernel_launch(void* const* d_in, const int* in_sizes, int n_in,
                              void* d_out, int out_size) {
    const float* x    = (const float*)d_in[0];
    const float* w    = (const float*)d_in[1];
    const float* bias = (const float*)d_in[2];
    float* out = (float*)d_out;
    (void)in_sizes; (void)n_in; (void)out_size;

    k_cvt_x<<<(TOKENS * KDIM / 4) / 256, 256>>>((const float4*)x);
    k_cvt_w<<<(NDIM * KDIM / 4) / 256, 256>>>((const float4*)w);

    cudaFuncSetAttribute(binlin_gemm,
                         cudaFuncAttributeMaxDynamicSharedMemorySize, SMEM_TOTAL);
    binlin_gemm<<<TILES_M * TILES_N, 256, SMEM_TOTAL>>>(bias, out);
}

// round 9
// speedup vs baseline: 1.1967x; 1.1967x over previous
#include <cuda_runtime.h>
#include <cuda_fp16.h>
#include <cstdint>

// ============================================================================
// BinaryLinear via 2:4 SPARSE tensor cores: y = x @ sign(W)^T + sign(b)
// Pair identity: s0*x0+s1*x1 = s0*(x0+x1) if s0s1>0 else s0*(x0-x1)
//  -> x' dense fp16 with (x0+x1, x0-x1) pairs
//  -> W' 2:4 sparse: one +-1 per pair; metadata nibble per 4-group:
//     (s0^s1) | ((2+(s2^s3))<<2)  (ordered)
// mma.sp::ordered_metadata.m16n8k32 halves tensor-op count vs dense.
// Metadata thread mapping (sm80 lineage, via CUTLASS reorder_meta):
//   T4i+0 = {lo: row i k0-15,  hi: row i+8 k0-15}
//   T4i+1 = {lo: row i k16-31, hi: row i+8 k16-31}
// ============================================================================

#define TOKENS 8192
#define KDIM   4096
#define NDIM   4096

#define BMN 128
#define BNT 256
#define BK  128
#define NKIT (KDIM / BK)            // 32
#define TILES_NF (NDIM / BMN)       // 32
#define TILES_T  (TOKENS / BNT)     // 32

#define A_BYTES   (BMN * 128)                  // 16KB compressed W
#define M_BYTES   2048                         // meta: 8 blk x 4 ks x 64B
#define B_OFF     (A_BYTES + M_BYTES)          // 18432
#define B_BYTES   (BNT * 256)                  // 64KB x'
#define STAGE_BYTES (B_OFF + B_BYTES)          // 83968
#define SMEM_TOTAL  (2 * STAGE_BYTES)          // 167936

__device__ __half   g_xp[(size_t)TOKENS * KDIM];
__device__ __half   g_wc[(size_t)NDIM * (KDIM / 2)];
// meta words: [n/16][ks32(128)][i(8)][khalf(2)] u32
__device__ uint32_t g_meta[(size_t)(NDIM / 16) * 128 * 16];

__device__ __forceinline__ uint32_t smem_u32(const void* p) {
    uint32_t a;
    asm("{ .reg .u64 t; cvta.to.shared.u64 t, %1; cvt.u32.u64 %0, t; }"
        : "=r"(a) : "l"(p));
    return a;
}
__device__ __forceinline__ void cp16(uint32_t saddr, const void* gaddr) {
    asm volatile("cp.async.cg.shared.global [%0], [%1], 16;"
                 :: "r"(saddr), "l"(gaddr));
}
__device__ __forceinline__ void ldsm4(uint32_t* r, uint32_t addr) {
    asm volatile("ldmatrix.sync.aligned.m8n8.x4.shared.b16 {%0,%1,%2,%3}, [%4];"
                 : "=r"(r[0]), "=r"(r[1]), "=r"(r[2]), "=r"(r[3]) : "r"(addr));
}
__device__ __forceinline__ void mma_sp(float* d, const uint32_t* a,
                                       uint32_t b0, uint32_t b1,
                                       uint32_t b2, uint32_t b3, uint32_t e) {
    asm volatile(
        "mma.sp::ordered_metadata.sync.aligned.m16n8k32.row.col.f32.f16.f16.f32 "
        "{%0,%1,%2,%3}, {%4,%5,%6,%7}, {%8,%9,%10,%11}, {%0,%1,%2,%3}, %12, 0x0;"
        : "+f"(d[0]), "+f"(d[1]), "+f"(d[2]), "+f"(d[3])
        : "r"(a[0]), "r"(a[1]), "r"(a[2]), "r"(a[3]),
          "r"(b0), "r"(b1), "r"(b2), "r"(b3), "r"(e));
}

// ---------------- pre-pass: x -> x' (p/m pairs, fp16) ----------------------
__global__ void __launch_bounds__(256) k_cvt_xp(const float4* __restrict__ x) {
    int i = blockIdx.x * 256 + threadIdx.x;
    float4 v = x[i];
    __half2 h0 = __floats2half2_rn(v.x + v.y, v.x - v.y);
    __half2 h1 = __floats2half2_rn(v.z + v.w, v.z - v.w);
    uint2 o;
    o.x = *reinterpret_cast<uint32_t*>(&h0);
    o.y = *reinterpret_cast<uint32_t*>(&h1);
    reinterpret_cast<uint2*>(g_xp)[i] = o;
}

// ---------------- pre-pass: W -> compressed vals + interleaved metadata ----
__global__ void __launch_bounds__(256) k_cvt_w(const float4* __restrict__ w) {
    int idx = blockIdx.x * 256 + threadIdx.x;   // 4096 * 128
    int n    = idx >> 7;
    int ks32 = idx & 127;
    const float4* src = w + ((size_t)n * KDIM + ks32 * 32) / 4;

    uint32_t meta = 0;
    uint16_t hv[16];
    #pragma unroll
    for (int g = 0; g < 8; g++) {
        float4 v = src[g];
        uint32_t s0 = (__float_as_uint(v.x) >> 31) & 1;
        uint32_t s1 = (__float_as_uint(v.y) >> 31) & 1;
        uint32_t s2 = (__float_as_uint(v.z) >> 31) & 1;
        uint32_t s3 = (__float_as_uint(v.w) >> 31) & 1;
        hv[2 * g]     = (uint16_t)(0x3C00u | (s0 << 15));
        hv[2 * g + 1] = (uint16_t)(0x3C00u | (s2 << 15));
        meta |= ((s0 ^ s1) | ((2u + (s2 ^ s3)) << 2)) << (4 * g);
    }
    uint4* dst = reinterpret_cast<uint4*>(g_wc + (size_t)n * (KDIM / 2) + ks32 * 16);
    dst[0] = *reinterpret_cast<uint4*>(&hv[0]);
    dst[1] = *reinterpret_cast<uint4*>(&hv[8]);

    // interleaved meta: word (blk, ks32, i, khalf); u16 half by (n>>3)&1
    uint16_t* mp = reinterpret_cast<uint16_t*>(g_meta);
    size_t wbase = (((size_t)(n >> 4) * 128 + ks32) * 16 + (uint32_t)(n & 7) * 2);
    uint32_t half = (n >> 3) & 1;
    mp[(wbase + 0) * 2 + half] = (uint16_t)(meta & 0xFFFF);   // k0-15 word
    mp[(wbase + 1) * 2 + half] = (uint16_t)(meta >> 16);      // k16-31 word
}

// ---------------- stage fill ----------------
__device__ __forceinline__ void load_stage(uint32_t sb, int buf,
                                           int n0, int t0, int kt, int tid) {
    uint32_t base = sb + (uint32_t)buf * STAGE_BYTES;
    {   // A (Wc): 128 rows x 128B, swizzle chunk ^ (row&7)
        const int c = tid & 7;
        const int row0 = tid >> 3;      // 0..31
        const __half* g = g_wc + (size_t)(n0 + row0) * (KDIM / 2) + kt * 64 + c * 8;
        uint32_t sw0 = (uint32_t)row0 * 128 + ((uint32_t)((row0 & 7) ^ c) << 4);
        #pragma unroll
        for (int it = 0; it < 4; it++)
            cp16(base + sw0 + (uint32_t)it * 32 * 128,
                 g + (size_t)it * 32 * (KDIM / 2));
    }
    if (tid < 128) {   // meta: 8 blk x 4 ks x 64B
        const int blk = tid >> 4;           // 16-row block within tile
        const int ks  = (tid >> 2) & 3;
        const int ch  = tid & 3;            // 16B chunk
        const uint32_t* g = g_meta
            + (((size_t)(n0 >> 4) + blk) * 128 + (size_t)kt * 4 + ks) * 16 + ch * 4;
        cp16(base + A_BYTES + (uint32_t)(blk * 256 + ks * 64 + ch * 16), g);
    }
    {   // B (x'): 256 rows x 256B, swizzle chunk ^ (row&7)
        const int c = tid & 15;
        const int row0 = tid >> 4;      // 0..15
        const __half* g = g_xp + (size_t)(t0 + row0) * KDIM + kt * BK + c * 8;
        uint32_t sw0 = (uint32_t)row0 * 256 + ((uint32_t)(c ^ (row0 & 7)) << 4);
        #pragma unroll
        for (int it = 0; it < 16; it++)
            cp16(base + B_OFF + sw0 + (uint32_t)it * 16 * 256,
                 g + (size_t)it * 16 * KDIM);
    }
}

// ---------------- sparse GEMM: 8 warps (2 n x 4 t), warp 64x64 ----------------
__global__ void __launch_bounds__(256, 1) binlin_gemm(const float* __restrict__ bias,
                                                      float* __restrict__ out) {
    extern __shared__ char smem[];
    const uint32_t sb = smem_u32(smem);
    const int tid = threadIdx.x;
    const int wid = tid >> 5;
    const int lid = tid & 31;

    const int tileNF = blockIdx.x % TILES_NF;
    const int tileT  = blockIdx.x / TILES_NF;
    const int n0 = tileNF * BMN;
    const int t0 = tileT * BNT;

    const int warpM = wid >> 2;               // 0..1  n-slice (64)
    const int warpN = wid & 3;                // 0..3  t-slice (64)

    const int rowa = warpM * 64 + (lid & 15);
    const int ka   = lid >> 4;
    const uint32_t offA0 = (uint32_t)rowa * 128;
    const int ra7 = lid & 7;

    const int rowb_base = warpN * 64 + (lid & 7) + ((lid >> 4) << 3);
    const int kb  = (lid >> 3) & 1;
    const int rb7 = lid & 7;

    // meta smem word offset for this lane: i = lid>>2, khalf = lid&1
    const uint32_t moff = (uint32_t)((lid >> 2) * 8 + (lid & 1) * 4);

    float acc[4][8][4];
    #pragma unroll
    for (int i = 0; i < 4; i++)
        #pragma unroll
        for (int j = 0; j < 8; j++)
            #pragma unroll
            for (int r = 0; r < 4; r++) acc[i][j][r] = 0.f;

    load_stage(sb, 0, n0, t0, 0, tid);
    asm volatile("cp.async.commit_group;" ::: "memory");

    int buf_rd = 0, buf_ld = 1;

    for (int kt = 0; kt < NKIT; kt++) {
        asm volatile("cp.async.wait_group 0;" ::: "memory");
        __syncthreads();

        if (kt + 1 < NKIT)
            load_stage(sb, buf_ld, n0, t0, kt + 1, tid);
        asm volatile("cp.async.commit_group;" ::: "memory");
        buf_ld ^= 1;

        const uint32_t bufA = sb + (uint32_t)buf_rd * STAGE_BYTES;
        const uint32_t bufM = bufA + A_BYTES;
        const uint32_t bufB = bufA + B_OFF;
        buf_rd ^= 1;

        #pragma unroll
        for (int ks = 0; ks < 4; ks++) {      // four k32 steps per kt
            uint32_t P[4][2][4];
            #pragma unroll
            for (int u = 0; u < 4; u++)
                #pragma unroll
                for (int h = 0; h < 2; h++) {
                    int ks2 = ks * 2 + h;
                    uint32_t bd = bufB + (uint32_t)(rowb_base + 16 * u) * 256
                                + ((uint32_t)((ks2 * 2 + kb) ^ rb7) << 4);
                    ldsm4(P[u][h], bd);
                }
            #pragma unroll
            for (int mi = 0; mi < 4; mi++) {
                uint32_t a_r[4];
                ldsm4(a_r, bufA + offA0 + (uint32_t)(mi * 16 * 128)
                           + ((uint32_t)((ks * 2 + ka) ^ ra7) << 4));
                uint32_t e;
                asm volatile("ld.shared.b32 %0, [%1];" : "=r"(e)
                    : "r"(bufM + (uint32_t)((warpM * 4 + mi) * 256 + ks * 64) + moff));
                #pragma unroll
                for (int tg = 0; tg < 8; tg++) {
                    const int u = tg >> 1;
                    const int eo = (tg & 1) * 2;
                    mma_sp(acc[mi][tg], a_r,
                           P[u][0][eo], P[u][0][eo + 1],
                           P[u][1][eo], P[u][1][eo + 1], e);
                }
            }
        }
    }

    // ---------------- epilogue: y[t][n] = acc + sign(bias[n]) ----------------
    const int n0w = n0 + warpM * 64;
    const int t0w = t0 + warpN * 64;
    const int qr = lid >> 2;
    const int qc = (lid & 3) * 2;

    float sbv[4][2];
    #pragma unroll
    for (int mi = 0; mi < 4; mi++) {
        sbv[mi][0] = bias[n0w + mi * 16 + qr]     >= 0.f ? 1.f : -1.f;
        sbv[mi][1] = bias[n0w + mi * 16 + qr + 8] >= 0.f ? 1.f : -1.f;
    }

    #pragma unroll
    for (int mi = 0; mi < 4; mi++) {
        const int nlo = n0w + mi * 16 + qr;
        #pragma unroll
        for (int tg = 0; tg < 8; tg++) {
            const int t = t0w + tg * 8 + qc;
            out[(size_t)t * NDIM + nlo]           = acc[mi][tg][0] + sbv[mi][0];
            out[(size_t)(t + 1) * NDIM + nlo]     = acc[mi][tg][1] + sbv[mi][0];
            out[(size_t)t * NDIM + nlo + 8]       = acc[mi][tg][2] + sbv[mi][1];
            out[(size_t)(t + 1) * NDIM + nlo + 8] = acc[mi][tg][3] + sbv[mi][1];
        }
    }
}

// ---------------- entry ----------------
extern "C" void kernel_launch(void* const* d_in, const int* in_sizes, int n_in,
                              void* d_out, int out_size) {
    const float* x    = (const float*)d_in[0];
    const float* w    = (const float*)d_in[1];
    const float* bias = (const float*)d_in[2];
    float* out = (float*)d_out;
    (void)in_sizes; (void)n_in; (void)out_size;

    k_cvt_xp<<<(TOKENS * KDIM / 4) / 256, 256>>>((const float4*)x);
    k_cvt_w<<<(NDIM * 128) / 256, 256>>>((const float4*)w);

    cudaFuncSetAttribute(binlin_gemm,
                         cudaFuncAttributeMaxDynamicSharedMemorySize, SMEM_TOTAL);
    binlin_gemm<<<TILES_NF * TILES_T, 256, SMEM_TOTAL>>>(bias, out);
}

// round 10
// speedup vs baseline: 1.2125x; 1.0132x over previous
#include <cuda_runtime.h>
#include <cuda_fp16.h>
#include <cstdint>

// ============================================================================
// BinaryLinear via 2:4 SPARSE tensor cores: y = x @ sign(W)^T + sign(b)
//  x' fp16 with (x0+x1, x0-x1) pairs; W' 2:4 sparse (one +-1 per pair);
//  mma.sp::ordered_metadata.m16n8k32. Metadata thread mapping:
//   T4i+0 = {lo: row i k0-15,  hi: row i+8 k0-15}
//   T4i+1 = {lo: row i k16-31, hi: row i+8 k16-31}
// R10: CTA tile 128(n) x 128(t), 2 CTAs/SM (4 warps/SMSP) to overlap
// ldsm/fill latency with sibling-CTA mma issue.
// ============================================================================

#define TOKENS 8192
#define KDIM   4096
#define NDIM   4096

#define BMN 128
#define BNT 128
#define BK  128
#define NKIT (KDIM / BK)            // 32
#define TILES_NF (NDIM / BMN)       // 32
#define TILES_T  (TOKENS / BNT)     // 64

#define A_BYTES   (BMN * 128)                  // 16KB compressed W
#define M_BYTES   2048                         // meta: 8 blk x 4 ks x 64B
#define B_OFF     (A_BYTES + M_BYTES)          // 18432
#define B_BYTES   (BNT * 256)                  // 32KB x'
#define STAGE_BYTES (B_OFF + B_BYTES)          // 51200
#define SMEM_TOTAL  (2 * STAGE_BYTES)          // 102400 -> 2 CTAs/SM

__device__ __half   g_xp[(size_t)TOKENS * KDIM];
__device__ __half   g_wc[(size_t)NDIM * (KDIM / 2)];
// meta words: [n/16][ks32(128)][i(8)][khalf(2)] u32
__device__ uint32_t g_meta[(size_t)(NDIM / 16) * 128 * 16];

__device__ __forceinline__ uint32_t smem_u32(const void* p) {
    uint32_t a;
    asm("{ .reg .u64 t; cvta.to.shared.u64 t, %1; cvt.u32.u64 %0, t; }"
        : "=r"(a) : "l"(p));
    return a;
}
__device__ __forceinline__ void cp16(uint32_t saddr, const void* gaddr) {
    asm volatile("cp.async.cg.shared.global [%0], [%1], 16;"
                 :: "r"(saddr), "l"(gaddr));
}
__device__ __forceinline__ void ldsm4(uint32_t* r, uint32_t addr) {
    asm volatile("ldmatrix.sync.aligned.m8n8.x4.shared.b16 {%0,%1,%2,%3}, [%4];"
                 : "=r"(r[0]), "=r"(r[1]), "=r"(r[2]), "=r"(r[3]) : "r"(addr));
}
__device__ __forceinline__ void mma_sp(float* d, const uint32_t* a,
                                       uint32_t b0, uint32_t b1,
                                       uint32_t b2, uint32_t b3, uint32_t e) {
    asm volatile(
        "mma.sp::ordered_metadata.sync.aligned.m16n8k32.row.col.f32.f16.f16.f32 "
        "{%0,%1,%2,%3}, {%4,%5,%6,%7}, {%8,%9,%10,%11}, {%0,%1,%2,%3}, %12, 0x0;"
        : "+f"(d[0]), "+f"(d[1]), "+f"(d[2]), "+f"(d[3])
        : "r"(a[0]), "r"(a[1]), "r"(a[2]), "r"(a[3]),
          "r"(b0), "r"(b1), "r"(b2), "r"(b3), "r"(e));
}

// ---------------- pre-pass: x -> x' (p/m pairs, fp16) ----------------------
__global__ void __launch_bounds__(256) k_cvt_xp(const float4* __restrict__ x) {
    int i = blockIdx.x * 256 + threadIdx.x;
    float4 v = x[i];
    __half2 h0 = __floats2half2_rn(v.x + v.y, v.x - v.y);
    __half2 h1 = __floats2half2_rn(v.z + v.w, v.z - v.w);
    uint2 o;
    o.x = *reinterpret_cast<uint32_t*>(&h0);
    o.y = *reinterpret_cast<uint32_t*>(&h1);
    reinterpret_cast<uint2*>(g_xp)[i] = o;
}

// ---------------- pre-pass: W -> compressed vals + interleaved metadata ----
__global__ void __launch_bounds__(256) k_cvt_w(const float4* __restrict__ w) {
    int idx = blockIdx.x * 256 + threadIdx.x;   // 4096 * 128
    int n    = idx >> 7;
    int ks32 = idx & 127;
    const float4* src = w + ((size_t)n * KDIM + ks32 * 32) / 4;

    uint32_t meta = 0;
    uint16_t hv[16];
    #pragma unroll
    for (int g = 0; g < 8; g++) {
        float4 v = src[g];
        uint32_t s0 = (__float_as_uint(v.x) >> 31) & 1;
        uint32_t s1 = (__float_as_uint(v.y) >> 31) & 1;
        uint32_t s2 = (__float_as_uint(v.z) >> 31) & 1;
        uint32_t s3 = (__float_as_uint(v.w) >> 31) & 1;
        hv[2 * g]     = (uint16_t)(0x3C00u | (s0 << 15));
        hv[2 * g + 1] = (uint16_t)(0x3C00u | (s2 << 15));
        meta |= ((s0 ^ s1) | ((2u + (s2 ^ s3)) << 2)) << (4 * g);
    }
    uint4* dst = reinterpret_cast<uint4*>(g_wc + (size_t)n * (KDIM / 2) + ks32 * 16);
    dst[0] = *reinterpret_cast<uint4*>(&hv[0]);
    dst[1] = *reinterpret_cast<uint4*>(&hv[8]);

    uint16_t* mp = reinterpret_cast<uint16_t*>(g_meta);
    size_t wbase = (((size_t)(n >> 4) * 128 + ks32) * 16 + (uint32_t)(n & 7) * 2);
    uint32_t half = (n >> 3) & 1;
    mp[(wbase + 0) * 2 + half] = (uint16_t)(meta & 0xFFFF);   // k0-15 word
    mp[(wbase + 1) * 2 + half] = (uint16_t)(meta >> 16);      // k16-31 word
}

// ---------------- stage fill ----------------
__device__ __forceinline__ void load_stage(uint32_t sb, int buf,
                                           int n0, int t0, int kt, int tid) {
    uint32_t base = sb + (uint32_t)buf * STAGE_BYTES;
    {   // A (Wc): 128 rows x 128B, swizzle chunk ^ (row&7); 4 cp16/thread
        const int c = tid & 7;
        const int row0 = tid >> 3;      // 0..31
        const __half* g = g_wc + (size_t)(n0 + row0) * (KDIM / 2) + kt * 64 + c * 8;
        uint32_t sw0 = (uint32_t)row0 * 128 + ((uint32_t)((row0 & 7) ^ c) << 4);
        #pragma unroll
        for (int it = 0; it < 4; it++)
            cp16(base + sw0 + (uint32_t)it * 32 * 128,
                 g + (size_t)it * 32 * (KDIM / 2));
    }
    if (tid < 128) {   // meta: 8 blk x 4 ks x 64B
        const int blk = tid >> 4;
        const int ks  = (tid >> 2) & 3;
        const int ch  = tid & 3;
        const uint32_t* g = g_meta
            + (((size_t)(n0 >> 4) + blk) * 128 + (size_t)kt * 4 + ks) * 16 + ch * 4;
        cp16(base + A_BYTES + (uint32_t)(blk * 256 + ks * 64 + ch * 16), g);
    }
    {   // B (x'): 128 rows x 256B, swizzle chunk ^ (row&7); 8 cp16/thread
        const int c = tid & 15;
        const int row0 = tid >> 4;      // 0..15
        const __half* g = g_xp + (size_t)(t0 + row0) * KDIM + kt * BK + c * 8;
        uint32_t sw0 = (uint32_t)row0 * 256 + ((uint32_t)(c ^ (row0 & 7)) << 4);
        #pragma unroll
        for (int it = 0; it < 8; it++)
            cp16(base + B_OFF + sw0 + (uint32_t)it * 16 * 256,
                 g + (size_t)it * 16 * KDIM);
    }
}

// ---------------- sparse GEMM: 8 warps (2 n x 4 t), warp 64x32 --------------
__global__ void __launch_bounds__(256, 2) binlin_gemm(const float* __restrict__ bias,
                                                      float* __restrict__ out) {
    extern __shared__ char smem[];
    const uint32_t sb = smem_u32(smem);
    const int tid = threadIdx.x;
    const int wid = tid >> 5;
    const int lid = tid & 31;

    const int tileNF = blockIdx.x % TILES_NF;   // inner: W reuse within wave
    const int tileT  = blockIdx.x / TILES_NF;
    const int n0 = tileNF * BMN;
    const int t0 = tileT * BNT;

    const int warpM = wid >> 2;               // 0..1  n-slice (64)
    const int warpN = wid & 3;                // 0..3  t-slice (32)

    const int rowa = warpM * 64 + (lid & 15);
    const int ka   = lid >> 4;
    const uint32_t offA0 = (uint32_t)rowa * 128;
    const int ra7 = lid & 7;

    const int rowb_base = warpN * 32 + (lid & 7) + ((lid >> 4) << 3);
    const int kb  = (lid >> 3) & 1;
    const int rb7 = lid & 7;

    const uint32_t moff = (uint32_t)((lid >> 2) * 8 + (lid & 1) * 4);

    float acc[4][4][4];
    #pragma unroll
    for (int i = 0; i < 4; i++)
        #pragma unroll
        for (int j = 0; j < 4; j++)
            #pragma unroll
            for (int r = 0; r < 4; r++) acc[i][j][r] = 0.f;

    load_stage(sb, 0, n0, t0, 0, tid);
    asm volatile("cp.async.commit_group;" ::: "memory");

    int buf_rd = 0, buf_ld = 1;

    for (int kt = 0; kt < NKIT; kt++) {
        asm volatile("cp.async.wait_group 0;" ::: "memory");
        __syncthreads();

        if (kt + 1 < NKIT)
            load_stage(sb, buf_ld, n0, t0, kt + 1, tid);
        asm volatile("cp.async.commit_group;" ::: "memory");
        buf_ld ^= 1;

        const uint32_t bufA = sb + (uint32_t)buf_rd * STAGE_BYTES;
        const uint32_t bufM = bufA + A_BYTES;
        const uint32_t bufB = bufA + B_OFF;
        buf_rd ^= 1;

        #pragma unroll
        for (int ks = 0; ks < 4; ks++) {      // four k32 steps per kt
            uint32_t P[2][2][4];
            #pragma unroll
            for (int u = 0; u < 2; u++)
                #pragma unroll
                for (int h = 0; h < 2; h++) {
                    int ks2 = ks * 2 + h;
                    uint32_t bd = bufB + (uint32_t)(rowb_base + 16 * u) * 256
                                + ((uint32_t)((ks2 * 2 + kb) ^ rb7) << 4);
                    ldsm4(P[u][h], bd);
                }
            #pragma unroll
            for (int mi = 0; mi < 4; mi++) {
                uint32_t a_r[4];
                ldsm4(a_r, bufA + offA0 + (uint32_t)(mi * 16 * 128)
                           + ((uint32_t)((ks * 2 + ka) ^ ra7) << 4));
                uint32_t e;
                asm volatile("ld.shared.b32 %0, [%1];" : "=r"(e)
                    : "r"(bufM + (uint32_t)((warpM * 4 + mi) * 256 + ks * 64) + moff));
                #pragma unroll
                for (int tg = 0; tg < 4; tg++) {
                    const int u = tg >> 1;
                    const int eo = (tg & 1) * 2;
                    mma_sp(acc[mi][tg], a_r,
                           P[u][0][eo], P[u][0][eo + 1],
                           P[u][1][eo], P[u][1][eo + 1], e);
                }
            }
        }
    }

    // ---------------- epilogue: y[t][n] = acc + sign(bias[n]) ----------------
    const int n0w = n0 + warpM * 64;
    const int t0w = t0 + warpN * 32;
    const int qr = lid >> 2;
    const int qc = (lid & 3) * 2;

    float sbv[4][2];
    #pragma unroll
    for (int mi = 0; mi < 4; mi++) {
        sbv[mi][0] = bias[n0w + mi * 16 + qr]     >= 0.f ? 1.f : -1.f;
        sbv[mi][1] = bias[n0w + mi * 16 + qr + 8] >= 0.f ? 1.f : -1.f;
    }

    #pragma unroll
    for (int mi = 0; mi < 4; mi++) {
        const int nlo = n0w + mi * 16 + qr;
        #pragma unroll
        for (int tg = 0; tg < 4; tg++) {
            const int t = t0w + tg * 8 + qc;
            out[(size_t)t * NDIM + nlo]           = acc[mi][tg][0] + sbv[mi][0];
            out[(size_t)(t + 1) * NDIM + nlo]     = acc[mi][tg][1] + sbv[mi][0];
            out[(size_t)t * NDIM + nlo + 8]       = acc[mi][tg][2] + sbv[mi][1];
            out[(size_t)(t + 1) * NDIM + nlo + 8] = acc[mi][tg][3] + sbv[mi][1];
        }
    }
}

// ---------------- entry ----------------
extern "C" void kernel_launch(void* const* d_in, const int* in_sizes, int n_in,
                              void* d_out, int out_size) {
    const float* x    = (const float*)d_in[0];
    const float* w    = (const float*)d_in[1];
    const float* bias = (const float*)d_in[2];
    float* out = (float*)d_out;
    (void)in_sizes; (void)n_in; (void)out_size;

    k_cvt_xp<<<(TOKENS * KDIM / 4) / 256, 256>>>((const float4*)x);
    k_cvt_w<<<(NDIM * 128) / 256, 256>>>((const float4*)w);

    cudaFuncSetAttribute(binlin_gemm,
                         cudaFuncAttributeMaxDynamicSharedMemorySize, SMEM_TOTAL);
    binlin_gemm<<<TILES_NF * TILES_T, 256, SMEM_TOTAL>>>(bias, out);
}